// round 1
// baseline (speedup 1.0000x reference)
#include <cuda_runtime.h>
#include <cuda_bf16.h>

// Problem constants
#define T   2048
#define D   2048
#define NH  16
#define DH  128
#define DRH 64
#define DC  512
#define QKD 192   // DH + DRH

// -------- scratch (device globals; no allocation allowed) --------
__device__ float g_ckv[(size_t)T * DC];            // kv latent   [t, c]
__device__ float g_cq [(size_t)T * DC];            // q latent    [t, c]
__device__ float g_q  [(size_t)NH * T * QKD];      // q concat    [n, t, 192]
__device__ float g_k  [(size_t)NH * T * QKD];      // k concat    [n, t, 192]
__device__ float g_v  [(size_t)NH * T * DH];       // v_c         [n, t, 128]
__device__ float g_kr [(size_t)T * DRH];           // k_r pre-rope [t, 64]
__device__ float g_logits[(size_t)NH * T * T];     // [n, t, l]
__device__ float g_attn[(size_t)T * NH * DH];      // [l, n*DH + e]
__device__ float g_wot [(size_t)D * NH * DH];      // [d, n*DH + e]

// ============================================================
// Generic tiled GEMMs (64x64 tile, BK=16, 256 threads, 4x4/thread)
// ============================================================
#define BM 64
#define BN 64
#define BK 16

// C[m,n] = sum_k A[m,k] * B[n,k]   (both row-major, contract last dims)
__global__ __launch_bounds__(256) void gemm_nt(
    const float* __restrict__ A, const float* __restrict__ B, float* __restrict__ C,
    int M, int N, int K, int lda, int ldb, int ldc,
    long long sA, long long sB, long long sC)
{
    __shared__ float As[BK][BM];
    __shared__ float Bs[BK][BN];
    A += (long long)blockIdx.z * sA;
    B += (long long)blockIdx.z * sB;
    C += (long long)blockIdx.z * sC;
    const int bm = blockIdx.y * BM;
    const int bn = blockIdx.x * BN;
    const int tid = threadIdx.x;
    const int tx = tid & 15;       // 0..15
    const int ty = tid >> 4;       // 0..15
    const int lrow = tid >> 2;       // 0..63
    const int lcol = (tid & 3) * 4;  // 0,4,8,12

    float acc[4][4] = {};

    for (int k0 = 0; k0 < K; k0 += BK) {
        float4 a = *(const float4*)(A + (long long)(bm + lrow) * lda + k0 + lcol);
        float4 b = *(const float4*)(B + (long long)(bn + lrow) * ldb + k0 + lcol);
        __syncthreads();
        As[lcol + 0][lrow] = a.x; As[lcol + 1][lrow] = a.y;
        As[lcol + 2][lrow] = a.z; As[lcol + 3][lrow] = a.w;
        Bs[lcol + 0][lrow] = b.x; Bs[lcol + 1][lrow] = b.y;
        Bs[lcol + 2][lrow] = b.z; Bs[lcol + 3][lrow] = b.w;
        __syncthreads();
#pragma unroll
        for (int kk = 0; kk < BK; ++kk) {
            float4 av = *(const float4*)(&As[kk][ty * 4]);
            float4 bv = *(const float4*)(&Bs[kk][tx * 4]);
            float a4[4] = {av.x, av.y, av.z, av.w};
            float b4[4] = {bv.x, bv.y, bv.z, bv.w};
#pragma unroll
            for (int i = 0; i < 4; ++i)
#pragma unroll
                for (int j = 0; j < 4; ++j)
                    acc[i][j] = fmaf(a4[i], b4[j], acc[i][j]);
        }
    }

    const int crow = bm + ty * 4;
    const int ccol = bn + tx * 4;
#pragma unroll
    for (int i = 0; i < 4; ++i) {
        float4 o = make_float4(acc[i][0], acc[i][1], acc[i][2], acc[i][3]);
        *(float4*)(C + (long long)(crow + i) * ldc + ccol) = o;
    }
}

// C[m,n] = sum_k A[k,m] * B[k,n]   (A: [K,M] row-major, B: [K,N] row-major)
__global__ __launch_bounds__(256) void gemm_tn(
    const float* __restrict__ A, const float* __restrict__ B, float* __restrict__ C,
    int M, int N, int K, int lda, int ldb, int ldc,
    long long sA, long long sB, long long sC)
{
    __shared__ float As[BK][BM];
    __shared__ float Bs[BK][BN];
    A += (long long)blockIdx.z * sA;
    B += (long long)blockIdx.z * sB;
    C += (long long)blockIdx.z * sC;
    const int bm = blockIdx.y * BM;
    const int bn = blockIdx.x * BN;
    const int tid = threadIdx.x;
    const int tx = tid & 15;
    const int ty = tid >> 4;
    const int kk_ld = tid >> 4;        // 0..15
    const int m4    = (tid & 15) * 4;  // 0..60

    float acc[4][4] = {};

    for (int k0 = 0; k0 < K; k0 += BK) {
        float4 a = *(const float4*)(A + (long long)(k0 + kk_ld) * lda + bm + m4);
        float4 b = *(const float4*)(B + (long long)(k0 + kk_ld) * ldb + bn + m4);
        __syncthreads();
        *(float4*)(&As[kk_ld][m4]) = a;
        *(float4*)(&Bs[kk_ld][m4]) = b;
        __syncthreads();
#pragma unroll
        for (int kk = 0; kk < BK; ++kk) {
            float4 av = *(const float4*)(&As[kk][ty * 4]);
            float4 bv = *(const float4*)(&Bs[kk][tx * 4]);
            float a4[4] = {av.x, av.y, av.z, av.w};
            float b4[4] = {bv.x, bv.y, bv.z, bv.w};
#pragma unroll
            for (int i = 0; i < 4; ++i)
#pragma unroll
                for (int j = 0; j < 4; ++j)
                    acc[i][j] = fmaf(a4[i], b4[j], acc[i][j]);
        }
    }

    const int crow = bm + ty * 4;
    const int ccol = bn + tx * 4;
#pragma unroll
    for (int i = 0; i < 4; ++i) {
        float4 o = make_float4(acc[i][0], acc[i][1], acc[i][2], acc[i][3]);
        *(float4*)(C + (long long)(crow + i) * ldc + ccol) = o;
    }
}

// ============================================================
// Elementwise kernels
// ============================================================

// In-place rope on q_r slice of g_q (cols 128..191 of each [n,t] row).
__global__ void rope_q_kernel(float* __restrict__ q, const float* __restrict__ freqs)
{
    int idx = blockIdx.x * blockDim.x + threadIdx.x;   // NH*T*32
    int i = idx & 31;
    int t = (idx >> 5) & (T - 1);
    int n = idx >> 16;
    float ang = freqs[t * (DRH / 2) + i];
    float c, s;
    __sincosf(ang, &s, &c);
    float* base = q + ((size_t)(n * T + t)) * QKD + DH;
    float re = base[i], im = base[i + 32];
    base[i]      = re * c - im * s;
    base[i + 32] = re * s + im * c;
}

// rope k_r then broadcast /NH into cols 128..191 of all heads of g_k.
__global__ void rope_k_bcast_kernel(const float* __restrict__ kr, float* __restrict__ kbuf,
                                    const float* __restrict__ freqs)
{
    int idx = blockIdx.x * blockDim.x + threadIdx.x;   // T*32
    int i = idx & 31;
    int t = idx >> 5;
    float ang = freqs[t * (DRH / 2) + i];
    float c, s;
    __sincosf(ang, &s, &c);
    float re = kr[t * DRH + i], im = kr[t * DRH + 32 + i];
    const float inv_nh = 1.0f / (float)NH;
    float rr = (re * c - im * s) * inv_nh;
    float ri = (re * s + im * c) * inv_nh;
#pragma unroll
    for (int n = 0; n < NH; ++n) {
        float* b = kbuf + ((size_t)(n * T + t)) * QKD + DH;
        b[i]      = rr;
        b[i + 32] = ri;
    }
}

// wt[d, n*DH+e] = w_o[d, e, n]  (w_o layout [D, DH, NH])
__global__ void wo_transpose_kernel(const float* __restrict__ wo, float* __restrict__ wt)
{
    int idx = blockIdx.x * blockDim.x + threadIdx.x;   // D * NH * DH
    int j = idx & (NH * DH - 1);
    int d = idx >> 11;
    int n = j >> 7;
    int e = j & (DH - 1);
    wt[idx] = wo[(size_t)d * (DH * NH) + e * NH + n];
}

// Row softmax over l: logits[n,t,l]*scale + mask[t,l], softmax, in place.
// One block per (t,n); 256 threads, 8 elems/thread held in registers.
__global__ __launch_bounds__(256) void softmax_kernel(
    float* __restrict__ logits, const float* __restrict__ mask, float scale)
{
    const int t = blockIdx.x;
    const int n = blockIdx.y;
    float* __restrict__ row = logits + ((size_t)n * T + t) * T;
    const float* __restrict__ mrow = mask + (size_t)t * T;
    const int tid = threadIdx.x;

    float v[8];
    float mx = -1e30f;
#pragma unroll
    for (int j = 0; j < 8; ++j) {
        int l = tid + j * 256;
        v[j] = fmaf(row[l], scale, mrow[l]);
        mx = fmaxf(mx, v[j]);
    }
    __shared__ float redm[8], reds[8];
#pragma unroll
    for (int o = 16; o; o >>= 1) mx = fmaxf(mx, __shfl_xor_sync(0xffffffffu, mx, o));
    if ((tid & 31) == 0) redm[tid >> 5] = mx;
    __syncthreads();
    mx = redm[0];
#pragma unroll
    for (int w = 1; w < 8; ++w) mx = fmaxf(mx, redm[w]);

    float sum = 0.0f;
#pragma unroll
    for (int j = 0; j < 8; ++j) {
        v[j] = __expf(v[j] - mx);
        sum += v[j];
    }
#pragma unroll
    for (int o = 16; o; o >>= 1) sum += __shfl_xor_sync(0xffffffffu, sum, o);
    if ((tid & 31) == 0) reds[tid >> 5] = sum;
    __syncthreads();
    sum = reds[0];
#pragma unroll
    for (int w = 1; w < 8; ++w) sum += reds[w];

    float inv = 1.0f / sum;
#pragma unroll
    for (int j = 0; j < 8; ++j)
        row[tid + j * 256] = v[j] * inv;
}

// ============================================================
// Launch
// ============================================================
extern "C" void kernel_launch(void* const* d_in, const int* in_sizes, int n_in,
                              void* d_out, int out_size)
{
    const float* h     = (const float*)d_in[0];
    const float* freqs = (const float*)d_in[1];
    const float* mask  = (const float*)d_in[2];
    const float* w_dkv = (const float*)d_in[3];
    const float* w_uk  = (const float*)d_in[4];
    const float* w_uv  = (const float*)d_in[5];
    const float* w_dq  = (const float*)d_in[6];
    const float* w_uq  = (const float*)d_in[7];
    const float* w_qr  = (const float*)d_in[8];
    const float* w_kr  = (const float*)d_in[9];
    const float* w_o   = (const float*)d_in[10];
    float* out = (float*)d_out;
    (void)in_sizes; (void)n_in; (void)out_size;

    float *ckv, *cq, *q, *k, *v, *kr, *logits, *attn, *wot;
    cudaGetSymbolAddress((void**)&ckv,    g_ckv);
    cudaGetSymbolAddress((void**)&cq,     g_cq);
    cudaGetSymbolAddress((void**)&q,      g_q);
    cudaGetSymbolAddress((void**)&k,      g_k);
    cudaGetSymbolAddress((void**)&v,      g_v);
    cudaGetSymbolAddress((void**)&kr,     g_kr);
    cudaGetSymbolAddress((void**)&logits, g_logits);
    cudaGetSymbolAddress((void**)&attn,   g_attn);
    cudaGetSymbolAddress((void**)&wot,    g_wot);

    const dim3 blk(256);
    const long long sQ = (long long)T * QKD;

    // Latents: c_kv, c_q = h @ W^T
    gemm_nt<<<dim3(DC / BN, T / BM, 1), blk>>>(h, w_dkv, ckv, T, DC, D, D, D, DC, 0, 0, 0);
    gemm_nt<<<dim3(DC / BN, T / BM, 1), blk>>>(h, w_dq,  cq,  T, DC, D, D, D, DC, 0, 0, 0);
    // k_r (pre-rope)
    gemm_nt<<<dim3(DRH / BN, T / BM, 1), blk>>>(h, w_kr, kr, T, DRH, D, D, D, DRH, 0, 0, 0);

    // Per-head up-projections (B batched via strideB = DC into packed [e, n, c] weights)
    gemm_nt<<<dim3(DH / BN, T / BM, NH), blk>>>(ckv, w_uk, k, T, DH, DC, DC, NH * DC, QKD, 0, DC, sQ);
    gemm_nt<<<dim3(DH / BN, T / BM, NH), blk>>>(ckv, w_uv, v, T, DH, DC, DC, NH * DC, DH,  0, DC, (long long)T * DH);
    gemm_nt<<<dim3(DH / BN, T / BM, NH), blk>>>(cq,  w_uq, q, T, DH, DC, DC, NH * DC, QKD, 0, DC, sQ);
    gemm_nt<<<dim3(DRH / BN, T / BM, NH), blk>>>(cq, w_qr, q + DH, T, DRH, DC, DC, NH * DC, QKD, 0, DC, sQ);

    // Rope
    rope_q_kernel<<<(NH * T * 32) / 256, 256>>>(q, freqs);
    rope_k_bcast_kernel<<<(T * 32) / 256, 256>>>(kr, k, freqs);

    // logits[n,t,l] = q . k
    gemm_nt<<<dim3(T / BN, T / BM, NH), blk>>>(q, k, logits, T, T, QKD, QKD, QKD, T, sQ, sQ, (long long)T * T);

    // softmax over l with mask, scale = 1/sqrt(192)
    softmax_kernel<<<dim3(T, NH), 256>>>(logits, mask, 0.07216878364870323f);

    // out[n,l,e] = sum_t S[n,t,l] v[n,t,e]   ->  attn[l, n*DH+e]
    gemm_tn<<<dim3(DH / BN, T / BM, NH), blk>>>(logits, v, attn, T, DH, T, T, DH, NH * DH,
                                                (long long)T * T, (long long)T * DH, DH);

    // w_o permute then final projection
    wo_transpose_kernel<<<(D * NH * DH) / 256, 256>>>(w_o, wot);
    gemm_nt<<<dim3(D / BN, T / BM, 1), blk>>>(attn, wot, out, T, D, NH * DH, NH * DH, NH * DH, D, 0, 0, 0);
}

// round 2
// speedup vs baseline: 1.1854x; 1.1854x over previous
#include <cuda_runtime.h>
#include <cuda_bf16.h>

// Problem constants
#define T   2048
#define D   2048
#define NH  16
#define DH  128
#define DRH 64
#define DC  512
#define QKD 192   // DH + DRH

// -------- scratch (device globals; no allocation allowed) --------
__device__ float g_ckv[(size_t)T * DC];            // kv latent   [t, c]
__device__ float g_cq [(size_t)T * DC];            // q latent    [t, c]
__device__ float g_q  [(size_t)NH * T * QKD];      // q concat    [n, t, 192]
__device__ float g_k  [(size_t)NH * T * QKD];      // k concat    [n, t, 192]
__device__ float g_v  [(size_t)NH * T * DH];       // v_c         [n, t, 128]
__device__ float g_kr [(size_t)T * DRH];           // k_r pre-rope [t, 64]
__device__ float g_logits[(size_t)NH * T * T];     // [n, t, l]
__device__ float g_attn[(size_t)T * NH * DH];      // [l, n*DH + e]
__device__ float g_wot [(size_t)D * NH * DH];      // [d, n*DH + e]

// ============================================================
// 128x128x16 tiled GEMMs, 256 threads, 8x8 per thread (2x2 of float4)
// ============================================================
#define BM 128
#define BN 128
#define BK 16
#define PAD 4

// C[m,n] = sum_k A[m,k] * B[n,k]   (both row-major, contract last dim)
__global__ __launch_bounds__(256) void gemm_nt128(
    const float* __restrict__ A, const float* __restrict__ B, float* __restrict__ C,
    int K, int lda, int ldb, int ldc,
    long long sA, long long sB, long long sC)
{
    __shared__ float As[BK][BM + PAD];
    __shared__ float Bs[BK][BN + PAD];
    A += (long long)blockIdx.z * sA;
    B += (long long)blockIdx.z * sB;
    C += (long long)blockIdx.z * sC;
    const int bm = blockIdx.y * BM;
    const int bn = blockIdx.x * BN;
    const int tid = threadIdx.x;
    const int tx = tid & 15;    // M-fragment index
    const int ty = tid >> 4;    // N-fragment index
    const int arow = tid >> 2;          // 0..63
    const int acol = (tid & 3) * 4;     // 0,4,8,12

    float4 a0, a1, b0, b1;
    a0 = *(const float4*)(A + (long long)(bm + arow)      * lda + acol);
    a1 = *(const float4*)(A + (long long)(bm + arow + 64) * lda + acol);
    b0 = *(const float4*)(B + (long long)(bn + arow)      * ldb + acol);
    b1 = *(const float4*)(B + (long long)(bn + arow + 64) * ldb + acol);

    float acc[2][2][4][4] = {};

    for (int k0 = 0; k0 < K; k0 += BK) {
        __syncthreads();
        As[acol + 0][arow] = a0.x; As[acol + 1][arow] = a0.y;
        As[acol + 2][arow] = a0.z; As[acol + 3][arow] = a0.w;
        As[acol + 0][arow + 64] = a1.x; As[acol + 1][arow + 64] = a1.y;
        As[acol + 2][arow + 64] = a1.z; As[acol + 3][arow + 64] = a1.w;
        Bs[acol + 0][arow] = b0.x; Bs[acol + 1][arow] = b0.y;
        Bs[acol + 2][arow] = b0.z; Bs[acol + 3][arow] = b0.w;
        Bs[acol + 0][arow + 64] = b1.x; Bs[acol + 1][arow + 64] = b1.y;
        Bs[acol + 2][arow + 64] = b1.z; Bs[acol + 3][arow + 64] = b1.w;
        __syncthreads();
        if (k0 + BK < K) {
            const int kn = k0 + BK;
            a0 = *(const float4*)(A + (long long)(bm + arow)      * lda + kn + acol);
            a1 = *(const float4*)(A + (long long)(bm + arow + 64) * lda + kn + acol);
            b0 = *(const float4*)(B + (long long)(bn + arow)      * ldb + kn + acol);
            b1 = *(const float4*)(B + (long long)(bn + arow + 64) * ldb + kn + acol);
        }
#pragma unroll
        for (int kk = 0; kk < BK; ++kk) {
            float4 av0 = *(const float4*)(&As[kk][tx * 4]);
            float4 av1 = *(const float4*)(&As[kk][tx * 4 + 64]);
            float4 bv0 = *(const float4*)(&Bs[kk][ty * 4]);
            float4 bv1 = *(const float4*)(&Bs[kk][ty * 4 + 64]);
            float am[2][4] = {{av0.x, av0.y, av0.z, av0.w}, {av1.x, av1.y, av1.z, av1.w}};
            float bn_[2][4] = {{bv0.x, bv0.y, bv0.z, bv0.w}, {bv1.x, bv1.y, bv1.z, bv1.w}};
#pragma unroll
            for (int im = 0; im < 2; ++im)
#pragma unroll
                for (int jm = 0; jm < 2; ++jm)
#pragma unroll
                    for (int i = 0; i < 4; ++i)
#pragma unroll
                        for (int j = 0; j < 4; ++j)
                            acc[im][jm][i][j] = fmaf(am[im][i], bn_[jm][j], acc[im][jm][i][j]);
        }
    }

#pragma unroll
    for (int im = 0; im < 2; ++im)
#pragma unroll
        for (int i = 0; i < 4; ++i) {
            const long long row = bm + im * 64 + tx * 4 + i;
#pragma unroll
            for (int jm = 0; jm < 2; ++jm) {
                float4 o = make_float4(acc[im][jm][i][0], acc[im][jm][i][1],
                                       acc[im][jm][i][2], acc[im][jm][i][3]);
                *(float4*)(C + row * ldc + bn + jm * 64 + ty * 4) = o;
            }
        }
}

// C[m,n] = sum_k A[k,m] * B[k,n]   (A: [K,M] row-major, B: [K,N] row-major)
__global__ __launch_bounds__(256) void gemm_tn128(
    const float* __restrict__ A, const float* __restrict__ B, float* __restrict__ C,
    int K, int lda, int ldb, int ldc,
    long long sA, long long sB, long long sC)
{
    __shared__ float As[BK][BM + PAD];
    __shared__ float Bs[BK][BN + PAD];
    A += (long long)blockIdx.z * sA;
    B += (long long)blockIdx.z * sB;
    C += (long long)blockIdx.z * sC;
    const int bm = blockIdx.y * BM;
    const int bn = blockIdx.x * BN;
    const int tid = threadIdx.x;
    const int tx = tid & 15;
    const int ty = tid >> 4;
    const int krow = tid >> 5;          // 0..7
    const int ccol = (tid & 31) * 4;    // 0..124

    float4 a0, a1, b0, b1;
    a0 = *(const float4*)(A + (long long)(krow)     * lda + bm + ccol);
    a1 = *(const float4*)(A + (long long)(krow + 8) * lda + bm + ccol);
    b0 = *(const float4*)(B + (long long)(krow)     * ldb + bn + ccol);
    b1 = *(const float4*)(B + (long long)(krow + 8) * ldb + bn + ccol);

    float acc[2][2][4][4] = {};

    for (int k0 = 0; k0 < K; k0 += BK) {
        __syncthreads();
        *(float4*)(&As[krow][ccol])     = a0;
        *(float4*)(&As[krow + 8][ccol]) = a1;
        *(float4*)(&Bs[krow][ccol])     = b0;
        *(float4*)(&Bs[krow + 8][ccol]) = b1;
        __syncthreads();
        if (k0 + BK < K) {
            const int kn = k0 + BK;
            a0 = *(const float4*)(A + (long long)(kn + krow)     * lda + bm + ccol);
            a1 = *(const float4*)(A + (long long)(kn + krow + 8) * lda + bm + ccol);
            b0 = *(const float4*)(B + (long long)(kn + krow)     * ldb + bn + ccol);
            b1 = *(const float4*)(B + (long long)(kn + krow + 8) * ldb + bn + ccol);
        }
#pragma unroll
        for (int kk = 0; kk < BK; ++kk) {
            float4 av0 = *(const float4*)(&As[kk][tx * 4]);
            float4 av1 = *(const float4*)(&As[kk][tx * 4 + 64]);
            float4 bv0 = *(const float4*)(&Bs[kk][ty * 4]);
            float4 bv1 = *(const float4*)(&Bs[kk][ty * 4 + 64]);
            float am[2][4] = {{av0.x, av0.y, av0.z, av0.w}, {av1.x, av1.y, av1.z, av1.w}};
            float bn_[2][4] = {{bv0.x, bv0.y, bv0.z, bv0.w}, {bv1.x, bv1.y, bv1.z, bv1.w}};
#pragma unroll
            for (int im = 0; im < 2; ++im)
#pragma unroll
                for (int jm = 0; jm < 2; ++jm)
#pragma unroll
                    for (int i = 0; i < 4; ++i)
#pragma unroll
                        for (int j = 0; j < 4; ++j)
                            acc[im][jm][i][j] = fmaf(am[im][i], bn_[jm][j], acc[im][jm][i][j]);
        }
    }

#pragma unroll
    for (int im = 0; im < 2; ++im)
#pragma unroll
        for (int i = 0; i < 4; ++i) {
            const long long row = bm + im * 64 + tx * 4 + i;
#pragma unroll
            for (int jm = 0; jm < 2; ++jm) {
                float4 o = make_float4(acc[im][jm][i][0], acc[im][jm][i][1],
                                       acc[im][jm][i][2], acc[im][jm][i][3]);
                *(float4*)(C + row * ldc + bn + jm * 64 + ty * 4) = o;
            }
        }
}

// ============================================================
// 64x64 GEMM (for N=64 cases: k_r, q_r)
// ============================================================
#define SM_ 64
#define SK_ 16
__global__ __launch_bounds__(256) void gemm_nt64(
    const float* __restrict__ A, const float* __restrict__ B, float* __restrict__ C,
    int K, int lda, int ldb, int ldc,
    long long sA, long long sB, long long sC)
{
    __shared__ float As[SK_][SM_];
    __shared__ float Bs[SK_][SM_];
    A += (long long)blockIdx.z * sA;
    B += (long long)blockIdx.z * sB;
    C += (long long)blockIdx.z * sC;
    const int bm = blockIdx.y * SM_;
    const int bn = blockIdx.x * SM_;
    const int tid = threadIdx.x;
    const int tx = tid & 15;
    const int ty = tid >> 4;
    const int lrow = tid >> 2;
    const int lcol = (tid & 3) * 4;

    float acc[4][4] = {};

    for (int k0 = 0; k0 < K; k0 += SK_) {
        float4 a = *(const float4*)(A + (long long)(bm + lrow) * lda + k0 + lcol);
        float4 b = *(const float4*)(B + (long long)(bn + lrow) * ldb + k0 + lcol);
        __syncthreads();
        As[lcol + 0][lrow] = a.x; As[lcol + 1][lrow] = a.y;
        As[lcol + 2][lrow] = a.z; As[lcol + 3][lrow] = a.w;
        Bs[lcol + 0][lrow] = b.x; Bs[lcol + 1][lrow] = b.y;
        Bs[lcol + 2][lrow] = b.z; Bs[lcol + 3][lrow] = b.w;
        __syncthreads();
#pragma unroll
        for (int kk = 0; kk < SK_; ++kk) {
            float4 av = *(const float4*)(&As[kk][ty * 4]);
            float4 bv = *(const float4*)(&Bs[kk][tx * 4]);
            float a4[4] = {av.x, av.y, av.z, av.w};
            float b4[4] = {bv.x, bv.y, bv.z, bv.w};
#pragma unroll
            for (int i = 0; i < 4; ++i)
#pragma unroll
                for (int j = 0; j < 4; ++j)
                    acc[i][j] = fmaf(a4[i], b4[j], acc[i][j]);
        }
    }

    const int crow = bm + ty * 4;
    const int ccol = bn + tx * 4;
#pragma unroll
    for (int i = 0; i < 4; ++i) {
        float4 o = make_float4(acc[i][0], acc[i][1], acc[i][2], acc[i][3]);
        *(float4*)(C + (long long)(crow + i) * ldc + ccol) = o;
    }
}

// ============================================================
// Elementwise kernels
// ============================================================

// In-place rope on q_r slice of g_q (cols 128..191 of each [n,t] row).
__global__ void rope_q_kernel(float* __restrict__ q, const float* __restrict__ freqs)
{
    int idx = blockIdx.x * blockDim.x + threadIdx.x;   // NH*T*32
    int i = idx & 31;
    int t = (idx >> 5) & (T - 1);
    int n = idx >> 16;
    float ang = freqs[t * (DRH / 2) + i];
    float c, s;
    __sincosf(ang, &s, &c);
    float* base = q + ((size_t)(n * T + t)) * QKD + DH;
    float re = base[i], im = base[i + 32];
    base[i]      = re * c - im * s;
    base[i + 32] = re * s + im * c;
}

// rope k_r then broadcast /NH into cols 128..191 of all heads of g_k.
__global__ void rope_k_bcast_kernel(const float* __restrict__ kr, float* __restrict__ kbuf,
                                    const float* __restrict__ freqs)
{
    int idx = blockIdx.x * blockDim.x + threadIdx.x;   // T*32
    int i = idx & 31;
    int t = idx >> 5;
    float ang = freqs[t * (DRH / 2) + i];
    float c, s;
    __sincosf(ang, &s, &c);
    float re = kr[t * DRH + i], im = kr[t * DRH + 32 + i];
    const float inv_nh = 1.0f / (float)NH;
    float rr = (re * c - im * s) * inv_nh;
    float ri = (re * s + im * c) * inv_nh;
#pragma unroll
    for (int n = 0; n < NH; ++n) {
        float* b = kbuf + ((size_t)(n * T + t)) * QKD + DH;
        b[i]      = rr;
        b[i + 32] = ri;
    }
}

// wt[d, n*DH+e] = w_o[d, e, n]  (w_o layout [D, DH, NH])
__global__ void wo_transpose_kernel(const float* __restrict__ wo, float* __restrict__ wt)
{
    int idx = blockIdx.x * blockDim.x + threadIdx.x;   // D * NH * DH
    int j = idx & (NH * DH - 1);
    int d = idx >> 11;
    int n = j >> 7;
    int e = j & (DH - 1);
    wt[idx] = wo[(size_t)d * (DH * NH) + e * NH + n];
}

// Row softmax over l: logits[n,t,l]*scale + mask[t,l], softmax, in place.
__global__ __launch_bounds__(256) void softmax_kernel(
    float* __restrict__ logits, const float* __restrict__ mask, float scale)
{
    const int t = blockIdx.x;
    const int n = blockIdx.y;
    float* __restrict__ row = logits + ((size_t)n * T + t) * T;
    const float* __restrict__ mrow = mask + (size_t)t * T;
    const int tid = threadIdx.x;

    float v[8];
    float mx = -1e30f;
#pragma unroll
    for (int j = 0; j < 8; ++j) {
        int l = tid + j * 256;
        v[j] = fmaf(row[l], scale, mrow[l]);
        mx = fmaxf(mx, v[j]);
    }
    __shared__ float redm[8], reds[8];
#pragma unroll
    for (int o = 16; o; o >>= 1) mx = fmaxf(mx, __shfl_xor_sync(0xffffffffu, mx, o));
    if ((tid & 31) == 0) redm[tid >> 5] = mx;
    __syncthreads();
    mx = redm[0];
#pragma unroll
    for (int w = 1; w < 8; ++w) mx = fmaxf(mx, redm[w]);

    float sum = 0.0f;
#pragma unroll
    for (int j = 0; j < 8; ++j) {
        v[j] = __expf(v[j] - mx);
        sum += v[j];
    }
#pragma unroll
    for (int o = 16; o; o >>= 1) sum += __shfl_xor_sync(0xffffffffu, sum, o);
    if ((tid & 31) == 0) reds[tid >> 5] = sum;
    __syncthreads();
    sum = reds[0];
#pragma unroll
    for (int w = 1; w < 8; ++w) sum += reds[w];

    float inv = 1.0f / sum;
#pragma unroll
    for (int j = 0; j < 8; ++j)
        row[tid + j * 256] = v[j] * inv;
}

// ============================================================
// Launch
// ============================================================
extern "C" void kernel_launch(void* const* d_in, const int* in_sizes, int n_in,
                              void* d_out, int out_size)
{
    const float* h     = (const float*)d_in[0];
    const float* freqs = (const float*)d_in[1];
    const float* mask  = (const float*)d_in[2];
    const float* w_dkv = (const float*)d_in[3];
    const float* w_uk  = (const float*)d_in[4];
    const float* w_uv  = (const float*)d_in[5];
    const float* w_dq  = (const float*)d_in[6];
    const float* w_uq  = (const float*)d_in[7];
    const float* w_qr  = (const float*)d_in[8];
    const float* w_kr  = (const float*)d_in[9];
    const float* w_o   = (const float*)d_in[10];
    float* out = (float*)d_out;
    (void)in_sizes; (void)n_in; (void)out_size;

    float *ckv, *cq, *q, *k, *v, *kr, *logits, *attn, *wot;
    cudaGetSymbolAddress((void**)&ckv,    g_ckv);
    cudaGetSymbolAddress((void**)&cq,     g_cq);
    cudaGetSymbolAddress((void**)&q,      g_q);
    cudaGetSymbolAddress((void**)&k,      g_k);
    cudaGetSymbolAddress((void**)&v,      g_v);
    cudaGetSymbolAddress((void**)&kr,     g_kr);
    cudaGetSymbolAddress((void**)&logits, g_logits);
    cudaGetSymbolAddress((void**)&attn,   g_attn);
    cudaGetSymbolAddress((void**)&wot,    g_wot);

    const dim3 blk(256);
    const long long sQ = (long long)T * QKD;

    // Latents: c_kv, c_q = h @ W^T   (M=2048, N=512, K=2048)
    gemm_nt128<<<dim3(DC / BN, T / BM, 1), blk>>>(h, w_dkv, ckv, D, D, D, DC, 0, 0, 0);
    gemm_nt128<<<dim3(DC / BN, T / BM, 1), blk>>>(h, w_dq,  cq,  D, D, D, DC, 0, 0, 0);
    // k_r (pre-rope): N=64
    gemm_nt64<<<dim3(1, T / SM_, 1), blk>>>(h, w_kr, kr, D, D, D, DRH, 0, 0, 0);

    // Per-head up-projections (N=128, K=512, batched over heads)
    gemm_nt128<<<dim3(1, T / BM, NH), blk>>>(ckv, w_uk, k, DC, DC, NH * DC, QKD, 0, DC, sQ);
    gemm_nt128<<<dim3(1, T / BM, NH), blk>>>(ckv, w_uv, v, DC, DC, NH * DC, DH,  0, DC, (long long)T * DH);
    gemm_nt128<<<dim3(1, T / BM, NH), blk>>>(cq,  w_uq, q, DC, DC, NH * DC, QKD, 0, DC, sQ);
    // q_r: N=64
    gemm_nt64<<<dim3(1, T / SM_, NH), blk>>>(cq, w_qr, q + DH, DC, DC, NH * DC, QKD, 0, DC, sQ);

    // Rope
    rope_q_kernel<<<(NH * T * 32) / 256, 256>>>(q, freqs);
    rope_k_bcast_kernel<<<(T * 32) / 256, 256>>>(kr, k, freqs);

    // logits[n,t,l] = q . k   (M=N=2048, K=192)
    gemm_nt128<<<dim3(T / BN, T / BM, NH), blk>>>(q, k, logits, QKD, QKD, QKD, T, sQ, sQ, (long long)T * T);

    // softmax over l with mask, scale = 1/sqrt(192)
    softmax_kernel<<<dim3(T, NH), 256>>>(logits, mask, 0.07216878364870323f);

    // out[n,l,e] = sum_t S[n,t,l] v[n,t,e]   ->  attn[l, n*DH+e]   (M=2048, N=128, K=2048)
    gemm_tn128<<<dim3(1, T / BM, NH), blk>>>(logits, v, attn, T, T, DH, NH * DH,
                                             (long long)T * T, (long long)T * DH, DH);

    // w_o permute then final projection (M=2048, N=2048, K=2048)
    wo_transpose_kernel<<<(D * NH * DH) / 256, 256>>>(w_o, wot);
    gemm_nt128<<<dim3(D / BN, T / BM, 1), blk>>>(attn, wot, out, NH * DH, NH * DH, NH * DH, D, 0, 0, 0);
}

// round 3
// speedup vs baseline: 1.2636x; 1.0659x over previous
#include <cuda_runtime.h>
#include <cuda_bf16.h>

// Problem constants
#define T   2048
#define D   2048
#define NH  16
#define DH  128
#define DRH 64
#define DC  512
#define QKD 192   // DH + DRH

// -------- scratch (device globals; no allocation allowed) --------
__device__ float g_ckv[(size_t)T * DC];            // kv latent   [t, c]
__device__ float g_cq [(size_t)T * DC];            // q latent    [t, c]
__device__ float g_q  [(size_t)NH * T * QKD];      // q concat    [n, t, 192]
__device__ float g_k  [(size_t)NH * T * QKD];      // k concat    [n, t, 192]
__device__ float g_v  [(size_t)NH * T * DH];       // v_c         [n, t, 128]
__device__ float g_kr [(size_t)T * DRH];           // k_r pre-rope [t, 64]
__device__ float g_logits[(size_t)NH * T * T];     // [n, t, l]
__device__ float g_attn[(size_t)T * NH * DH];      // [l, n*DH + e]
__device__ float g_wot [(size_t)D * NH * DH];      // [d, n*DH + e]

typedef unsigned long long ull;

__device__ __forceinline__ void ffma2(ull& d, ull a, ull b) {
    asm("fma.rn.f32x2 %0, %1, %2, %0;" : "+l"(d) : "l"(a), "l"(b));
}
__device__ __forceinline__ ull dup2(float x) {
    ull r;
    asm("mov.b64 %0, {%1, %1};" : "=l"(r) : "f"(x));
    return r;
}
union F2u { ull u; float2 f; };

// ============================================================
// 128x128x16 tiled GEMMs, 256 threads, 8x8 per thread, FFMA2 mainloop
// ============================================================
#define BM 128
#define BN 128
#define BK 16
#define PAD 4

// C[m,n] = sum_k A[m,k] * B[n,k]   (both row-major, contract last dim)
__global__ __launch_bounds__(256) void gemm_nt128(
    const float* __restrict__ A, const float* __restrict__ B, float* __restrict__ C,
    int K, int lda, int ldb, int ldc,
    long long sA, long long sB, long long sC)
{
    __shared__ float As[BK][BM + PAD];
    __shared__ float Bs[BK][BN + PAD];
    A += (long long)blockIdx.z * sA;
    B += (long long)blockIdx.z * sB;
    C += (long long)blockIdx.z * sC;
    const int bm = blockIdx.y * BM;
    const int bn = blockIdx.x * BN;
    const int tid = threadIdx.x;
    const int tx = tid & 15;    // M-fragment index
    const int ty = tid >> 4;    // N-fragment index
    const int arow = tid >> 2;          // 0..63
    const int acol = (tid & 3) * 4;     // 0,4,8,12

    float4 a0, a1, b0, b1;
    a0 = *(const float4*)(A + (long long)(bm + arow)      * lda + acol);
    a1 = *(const float4*)(A + (long long)(bm + arow + 64) * lda + acol);
    b0 = *(const float4*)(B + (long long)(bn + arow)      * ldb + acol);
    b1 = *(const float4*)(B + (long long)(bn + arow + 64) * ldb + acol);

    // acc2[p][j]: p = M-pair index (4 pairs = 8 rows), j = N value (8)
    ull acc2[4][8] = {};

    for (int k0 = 0; k0 < K; k0 += BK) {
        __syncthreads();
        As[acol + 0][arow] = a0.x; As[acol + 1][arow] = a0.y;
        As[acol + 2][arow] = a0.z; As[acol + 3][arow] = a0.w;
        As[acol + 0][arow + 64] = a1.x; As[acol + 1][arow + 64] = a1.y;
        As[acol + 2][arow + 64] = a1.z; As[acol + 3][arow + 64] = a1.w;
        Bs[acol + 0][arow] = b0.x; Bs[acol + 1][arow] = b0.y;
        Bs[acol + 2][arow] = b0.z; Bs[acol + 3][arow] = b0.w;
        Bs[acol + 0][arow + 64] = b1.x; Bs[acol + 1][arow + 64] = b1.y;
        Bs[acol + 2][arow + 64] = b1.z; Bs[acol + 3][arow + 64] = b1.w;
        __syncthreads();
        if (k0 + BK < K) {
            const int kn = k0 + BK;
            a0 = *(const float4*)(A + (long long)(bm + arow)      * lda + kn + acol);
            a1 = *(const float4*)(A + (long long)(bm + arow + 64) * lda + kn + acol);
            b0 = *(const float4*)(B + (long long)(bn + arow)      * ldb + kn + acol);
            b1 = *(const float4*)(B + (long long)(bn + arow + 64) * ldb + kn + acol);
        }
#pragma unroll
        for (int kk = 0; kk < BK; ++kk) {
            float4 av0 = *(const float4*)(&As[kk][tx * 4]);
            float4 av1 = *(const float4*)(&As[kk][tx * 4 + 64]);
            float4 bv0 = *(const float4*)(&Bs[kk][ty * 4]);
            float4 bv1 = *(const float4*)(&Bs[kk][ty * 4 + 64]);
            ull ap[4];
            ap[0] = ((const ull*)&av0)[0];   // (a0,a1)
            ap[1] = ((const ull*)&av0)[1];   // (a2,a3)
            ap[2] = ((const ull*)&av1)[0];
            ap[3] = ((const ull*)&av1)[1];
            ull bb[8];
            bb[0] = dup2(bv0.x); bb[1] = dup2(bv0.y);
            bb[2] = dup2(bv0.z); bb[3] = dup2(bv0.w);
            bb[4] = dup2(bv1.x); bb[5] = dup2(bv1.y);
            bb[6] = dup2(bv1.z); bb[7] = dup2(bv1.w);
#pragma unroll
            for (int p = 0; p < 4; ++p)
#pragma unroll
                for (int j = 0; j < 8; ++j)
                    ffma2(acc2[p][j], ap[p], bb[j]);
        }
    }

    // p covers rows: m = bm + (p>>1)*64 + tx*4 + (p&1)*2 + {0,1}
    // j covers cols: n = bn + (j>>2)*64 + ty*4 + (j&3)
#pragma unroll
    for (int p = 0; p < 4; ++p) {
#pragma unroll
        for (int half = 0; half < 2; ++half) {
            const long long row = bm + (p >> 1) * 64 + tx * 4 + (p & 1) * 2 + half;
#pragma unroll
            for (int jm = 0; jm < 2; ++jm) {
                F2u v0, v1, v2, v3;
                v0.u = acc2[p][jm * 4 + 0];
                v1.u = acc2[p][jm * 4 + 1];
                v2.u = acc2[p][jm * 4 + 2];
                v3.u = acc2[p][jm * 4 + 3];
                float4 o = half ? make_float4(v0.f.y, v1.f.y, v2.f.y, v3.f.y)
                                : make_float4(v0.f.x, v1.f.x, v2.f.x, v3.f.x);
                *(float4*)(C + row * ldc + bn + jm * 64 + ty * 4) = o;
            }
        }
    }
}

// C[m,n] = sum_k A[k,m] * B[k,n]   (A: [K,M] row-major, B: [K,N] row-major)
__global__ __launch_bounds__(256) void gemm_tn128(
    const float* __restrict__ A, const float* __restrict__ B, float* __restrict__ C,
    int K, int lda, int ldb, int ldc,
    long long sA, long long sB, long long sC)
{
    __shared__ float As[BK][BM + PAD];
    __shared__ float Bs[BK][BN + PAD];
    A += (long long)blockIdx.z * sA;
    B += (long long)blockIdx.z * sB;
    C += (long long)blockIdx.z * sC;
    const int bm = blockIdx.y * BM;
    const int bn = blockIdx.x * BN;
    const int tid = threadIdx.x;
    const int tx = tid & 15;
    const int ty = tid >> 4;
    const int krow = tid >> 5;          // 0..7
    const int ccol = (tid & 31) * 4;    // 0..124

    float4 a0, a1, b0, b1;
    a0 = *(const float4*)(A + (long long)(krow)     * lda + bm + ccol);
    a1 = *(const float4*)(A + (long long)(krow + 8) * lda + bm + ccol);
    b0 = *(const float4*)(B + (long long)(krow)     * ldb + bn + ccol);
    b1 = *(const float4*)(B + (long long)(krow + 8) * ldb + bn + ccol);

    ull acc2[4][8] = {};

    for (int k0 = 0; k0 < K; k0 += BK) {
        __syncthreads();
        *(float4*)(&As[krow][ccol])     = a0;
        *(float4*)(&As[krow + 8][ccol]) = a1;
        *(float4*)(&Bs[krow][ccol])     = b0;
        *(float4*)(&Bs[krow + 8][ccol]) = b1;
        __syncthreads();
        if (k0 + BK < K) {
            const int kn = k0 + BK;
            a0 = *(const float4*)(A + (long long)(kn + krow)     * lda + bm + ccol);
            a1 = *(const float4*)(A + (long long)(kn + krow + 8) * lda + bm + ccol);
            b0 = *(const float4*)(B + (long long)(kn + krow)     * ldb + bn + ccol);
            b1 = *(const float4*)(B + (long long)(kn + krow + 8) * ldb + bn + ccol);
        }
#pragma unroll
        for (int kk = 0; kk < BK; ++kk) {
            float4 av0 = *(const float4*)(&As[kk][tx * 4]);
            float4 av1 = *(const float4*)(&As[kk][tx * 4 + 64]);
            float4 bv0 = *(const float4*)(&Bs[kk][ty * 4]);
            float4 bv1 = *(const float4*)(&Bs[kk][ty * 4 + 64]);
            ull ap[4];
            ap[0] = ((const ull*)&av0)[0];
            ap[1] = ((const ull*)&av0)[1];
            ap[2] = ((const ull*)&av1)[0];
            ap[3] = ((const ull*)&av1)[1];
            ull bb[8];
            bb[0] = dup2(bv0.x); bb[1] = dup2(bv0.y);
            bb[2] = dup2(bv0.z); bb[3] = dup2(bv0.w);
            bb[4] = dup2(bv1.x); bb[5] = dup2(bv1.y);
            bb[6] = dup2(bv1.z); bb[7] = dup2(bv1.w);
#pragma unroll
            for (int p = 0; p < 4; ++p)
#pragma unroll
                for (int j = 0; j < 8; ++j)
                    ffma2(acc2[p][j], ap[p], bb[j]);
        }
    }

#pragma unroll
    for (int p = 0; p < 4; ++p) {
#pragma unroll
        for (int half = 0; half < 2; ++half) {
            const long long row = bm + (p >> 1) * 64 + tx * 4 + (p & 1) * 2 + half;
#pragma unroll
            for (int jm = 0; jm < 2; ++jm) {
                F2u v0, v1, v2, v3;
                v0.u = acc2[p][jm * 4 + 0];
                v1.u = acc2[p][jm * 4 + 1];
                v2.u = acc2[p][jm * 4 + 2];
                v3.u = acc2[p][jm * 4 + 3];
                float4 o = half ? make_float4(v0.f.y, v1.f.y, v2.f.y, v3.f.y)
                                : make_float4(v0.f.x, v1.f.x, v2.f.x, v3.f.x);
                *(float4*)(C + row * ldc + bn + jm * 64 + ty * 4) = o;
            }
        }
    }
}

// ============================================================
// 64x64 GEMM (for N=64 cases: k_r, q_r), FFMA2 mainloop
// ============================================================
#define SM_ 64
#define SK_ 16
__global__ __launch_bounds__(256) void gemm_nt64(
    const float* __restrict__ A, const float* __restrict__ B, float* __restrict__ C,
    int K, int lda, int ldb, int ldc,
    long long sA, long long sB, long long sC)
{
    __shared__ float As[SK_][SM_];
    __shared__ float Bs[SK_][SM_];
    A += (long long)blockIdx.z * sA;
    B += (long long)blockIdx.z * sB;
    C += (long long)blockIdx.z * sC;
    const int bm = blockIdx.y * SM_;
    const int bn = blockIdx.x * SM_;
    const int tid = threadIdx.x;
    const int tx = tid & 15;
    const int ty = tid >> 4;
    const int lrow = tid >> 2;
    const int lcol = (tid & 3) * 4;

    ull acc2[2][4] = {};

    for (int k0 = 0; k0 < K; k0 += SK_) {
        float4 a = *(const float4*)(A + (long long)(bm + lrow) * lda + k0 + lcol);
        float4 b = *(const float4*)(B + (long long)(bn + lrow) * ldb + k0 + lcol);
        __syncthreads();
        As[lcol + 0][lrow] = a.x; As[lcol + 1][lrow] = a.y;
        As[lcol + 2][lrow] = a.z; As[lcol + 3][lrow] = a.w;
        Bs[lcol + 0][lrow] = b.x; Bs[lcol + 1][lrow] = b.y;
        Bs[lcol + 2][lrow] = b.z; Bs[lcol + 3][lrow] = b.w;
        __syncthreads();
#pragma unroll
        for (int kk = 0; kk < SK_; ++kk) {
            float4 av = *(const float4*)(&As[kk][ty * 4]);
            float4 bv = *(const float4*)(&Bs[kk][tx * 4]);
            ull ap[2];
            ap[0] = ((const ull*)&av)[0];
            ap[1] = ((const ull*)&av)[1];
            ull bb[4];
            bb[0] = dup2(bv.x); bb[1] = dup2(bv.y);
            bb[2] = dup2(bv.z); bb[3] = dup2(bv.w);
#pragma unroll
            for (int p = 0; p < 2; ++p)
#pragma unroll
                for (int j = 0; j < 4; ++j)
                    ffma2(acc2[p][j], ap[p], bb[j]);
        }
    }

#pragma unroll
    for (int p = 0; p < 2; ++p) {
#pragma unroll
        for (int half = 0; half < 2; ++half) {
            const int crow = bm + ty * 4 + p * 2 + half;
            F2u v0, v1, v2, v3;
            v0.u = acc2[p][0]; v1.u = acc2[p][1];
            v2.u = acc2[p][2]; v3.u = acc2[p][3];
            float4 o = half ? make_float4(v0.f.y, v1.f.y, v2.f.y, v3.f.y)
                            : make_float4(v0.f.x, v1.f.x, v2.f.x, v3.f.x);
            *(float4*)(C + (long long)crow * ldc + bn + tx * 4) = o;
        }
    }
}

// ============================================================
// Elementwise kernels
// ============================================================

// In-place rope on q_r slice of g_q (cols 128..191 of each [n,t] row).
__global__ void rope_q_kernel(float* __restrict__ q, const float* __restrict__ freqs)
{
    int idx = blockIdx.x * blockDim.x + threadIdx.x;   // NH*T*32
    int i = idx & 31;
    int t = (idx >> 5) & (T - 1);
    int n = idx >> 16;
    float ang = freqs[t * (DRH / 2) + i];
    float c, s;
    __sincosf(ang, &s, &c);
    float* base = q + ((size_t)(n * T + t)) * QKD + DH;
    float re = base[i], im = base[i + 32];
    base[i]      = re * c - im * s;
    base[i + 32] = re * s + im * c;
}

// rope k_r then broadcast /NH into cols 128..191 of all heads of g_k.
__global__ void rope_k_bcast_kernel(const float* __restrict__ kr, float* __restrict__ kbuf,
                                    const float* __restrict__ freqs)
{
    int idx = blockIdx.x * blockDim.x + threadIdx.x;   // T*32
    int i = idx & 31;
    int t = idx >> 5;
    float ang = freqs[t * (DRH / 2) + i];
    float c, s;
    __sincosf(ang, &s, &c);
    float re = kr[t * DRH + i], im = kr[t * DRH + 32 + i];
    const float inv_nh = 1.0f / (float)NH;
    float rr = (re * c - im * s) * inv_nh;
    float ri = (re * s + im * c) * inv_nh;
#pragma unroll
    for (int n = 0; n < NH; ++n) {
        float* b = kbuf + ((size_t)(n * T + t)) * QKD + DH;
        b[i]      = rr;
        b[i + 32] = ri;
    }
}

// wt[d, n*DH+e] = w_o[d, e, n]  (w_o layout [D, DH, NH])
__global__ void wo_transpose_kernel(const float* __restrict__ wo, float* __restrict__ wt)
{
    int idx = blockIdx.x * blockDim.x + threadIdx.x;   // D * NH * DH
    int j = idx & (NH * DH - 1);
    int d = idx >> 11;
    int n = j >> 7;
    int e = j & (DH - 1);
    wt[idx] = wo[(size_t)d * (DH * NH) + e * NH + n];
}

// Row softmax over l: logits[n,t,l]*scale + mask[t,l], softmax, in place.
__global__ __launch_bounds__(256) void softmax_kernel(
    float* __restrict__ logits, const float* __restrict__ mask, float scale)
{
    const int t = blockIdx.x;
    const int n = blockIdx.y;
    float* __restrict__ row = logits + ((size_t)n * T + t) * T;
    const float* __restrict__ mrow = mask + (size_t)t * T;
    const int tid = threadIdx.x;

    float v[8];
    float mx = -1e30f;
#pragma unroll
    for (int j = 0; j < 8; ++j) {
        int l = tid + j * 256;
        v[j] = fmaf(row[l], scale, mrow[l]);
        mx = fmaxf(mx, v[j]);
    }
    __shared__ float redm[8], reds[8];
#pragma unroll
    for (int o = 16; o; o >>= 1) mx = fmaxf(mx, __shfl_xor_sync(0xffffffffu, mx, o));
    if ((tid & 31) == 0) redm[tid >> 5] = mx;
    __syncthreads();
    mx = redm[0];
#pragma unroll
    for (int w = 1; w < 8; ++w) mx = fmaxf(mx, redm[w]);

    float sum = 0.0f;
#pragma unroll
    for (int j = 0; j < 8; ++j) {
        v[j] = __expf(v[j] - mx);
        sum += v[j];
    }
#pragma unroll
    for (int o = 16; o; o >>= 1) sum += __shfl_xor_sync(0xffffffffu, sum, o);
    if ((tid & 31) == 0) reds[tid >> 5] = sum;
    __syncthreads();
    sum = reds[0];
#pragma unroll
    for (int w = 1; w < 8; ++w) sum += reds[w];

    float inv = 1.0f / sum;
#pragma unroll
    for (int j = 0; j < 8; ++j)
        row[tid + j * 256] = v[j] * inv;
}

// ============================================================
// Launch
// ============================================================
extern "C" void kernel_launch(void* const* d_in, const int* in_sizes, int n_in,
                              void* d_out, int out_size)
{
    const float* h     = (const float*)d_in[0];
    const float* freqs = (const float*)d_in[1];
    const float* mask  = (const float*)d_in[2];
    const float* w_dkv = (const float*)d_in[3];
    const float* w_uk  = (const float*)d_in[4];
    const float* w_uv  = (const float*)d_in[5];
    const float* w_dq  = (const float*)d_in[6];
    const float* w_uq  = (const float*)d_in[7];
    const float* w_qr  = (const float*)d_in[8];
    const float* w_kr  = (const float*)d_in[9];
    const float* w_o   = (const float*)d_in[10];
    float* out = (float*)d_out;
    (void)in_sizes; (void)n_in; (void)out_size;

    float *ckv, *cq, *q, *k, *v, *kr, *logits, *attn, *wot;
    cudaGetSymbolAddress((void**)&ckv,    g_ckv);
    cudaGetSymbolAddress((void**)&cq,     g_cq);
    cudaGetSymbolAddress((void**)&q,      g_q);
    cudaGetSymbolAddress((void**)&k,      g_k);
    cudaGetSymbolAddress((void**)&v,      g_v);
    cudaGetSymbolAddress((void**)&kr,     g_kr);
    cudaGetSymbolAddress((void**)&logits, g_logits);
    cudaGetSymbolAddress((void**)&attn,   g_attn);
    cudaGetSymbolAddress((void**)&wot,    g_wot);

    const dim3 blk(256);
    const long long sQ = (long long)T * QKD;

    // Latents: c_kv, c_q = h @ W^T   (M=2048, N=512, K=2048)
    gemm_nt128<<<dim3(DC / BN, T / BM, 1), blk>>>(h, w_dkv, ckv, D, D, D, DC, 0, 0, 0);
    gemm_nt128<<<dim3(DC / BN, T / BM, 1), blk>>>(h, w_dq,  cq,  D, D, D, DC, 0, 0, 0);
    // k_r (pre-rope): N=64
    gemm_nt64<<<dim3(1, T / SM_, 1), blk>>>(h, w_kr, kr, D, D, D, DRH, 0, 0, 0);

    // Per-head up-projections (N=128, K=512, batched over heads)
    gemm_nt128<<<dim3(1, T / BM, NH), blk>>>(ckv, w_uk, k, DC, DC, NH * DC, QKD, 0, DC, sQ);
    gemm_nt128<<<dim3(1, T / BM, NH), blk>>>(ckv, w_uv, v, DC, DC, NH * DC, DH,  0, DC, (long long)T * DH);
    gemm_nt128<<<dim3(1, T / BM, NH), blk>>>(cq,  w_uq, q, DC, DC, NH * DC, QKD, 0, DC, sQ);
    // q_r: N=64
    gemm_nt64<<<dim3(1, T / SM_, NH), blk>>>(cq, w_qr, q + DH, DC, DC, NH * DC, QKD, 0, DC, sQ);

    // Rope
    rope_q_kernel<<<(NH * T * 32) / 256, 256>>>(q, freqs);
    rope_k_bcast_kernel<<<(T * 32) / 256, 256>>>(kr, k, freqs);

    // logits[n,t,l] = q . k   (M=N=2048, K=192)
    gemm_nt128<<<dim3(T / BN, T / BM, NH), blk>>>(q, k, logits, QKD, QKD, QKD, T, sQ, sQ, (long long)T * T);

    // softmax over l with mask, scale = 1/sqrt(192)
    softmax_kernel<<<dim3(T, NH), 256>>>(logits, mask, 0.07216878364870323f);

    // out[n,l,e] = sum_t S[n,t,l] v[n,t,e]   ->  attn[l, n*DH+e]   (M=2048, N=128, K=2048)
    gemm_tn128<<<dim3(1, T / BM, NH), blk>>>(logits, v, attn, T, T, DH, NH * DH,
                                             (long long)T * T, (long long)T * DH, DH);

    // w_o permute then final projection (M=2048, N=2048, K=2048)
    wo_transpose_kernel<<<(D * NH * DH) / 256, 256>>>(w_o, wot);
    gemm_nt128<<<dim3(D / BN, T / BM, 1), blk>>>(attn, wot, out, NH * DH, NH * DH, NH * DH, D, 0, 0, 0);
}